// round 4
// baseline (speedup 1.0000x reference)
#include <cuda_runtime.h>
#include <cuda_bf16.h>

#define N_    4096
#define FIN_  500
#define H_    64
#define C_    7
#define E_    65536
#define B_    1024
#define A_    20
#define NW_   128          // bitset words per row (4096 bits)
#define CH_   (C_*H_)      // 448
#define HB_   (1 << 16)    // 16-bit histogram bins
#define CAP_  2048         // candidate cap in k_pick

// ---------------- scratch (device globals; zero at module load) -------------
__device__ float    g_embed[N_*H_];        // 1 MB
__device__ unsigned g_adj  [N_*NW_];       // 2 MB
__device__ unsigned g_hop2 [N_*NW_];       // 2 MB
__device__ int      g_cls  [N_];
__device__ float    g_thresh;
__device__ int      g_hist [HB_];          // 256 KB
__device__ float    g_red[3*B_*CH_];       // 5.5 MB

// ---------------- packed f32x2 helpers --------------------------------------
__device__ __forceinline__ unsigned long long pack2(float lo, float hi) {
    unsigned long long v;
    asm("mov.b64 %0, {%1, %2};" : "=l"(v) : "f"(lo), "f"(hi));
    return v;
}
__device__ __forceinline__ void unpack2(unsigned long long v, float& lo, float& hi) {
    asm("mov.b64 {%0, %1}, %2;" : "=f"(lo), "=f"(hi) : "l"(v));
}
__device__ __forceinline__ void fma2(unsigned long long& d,
                                     unsigned long long a, unsigned long long b) {
    asm("fma.rn.f32x2 %0, %1, %2, %0;" : "+l"(d) : "l"(a), "l"(b));
}

// ---------------- 1a) histogram of edge weights + zero g_adj ----------------
// g_hist arrives zeroed (module load on run 1, k_pick self-zero afterwards).
__global__ void k_hist(const float* __restrict__ w) {
    int i = blockIdx.x * blockDim.x + threadIdx.x;       // 65536 threads
    unsigned key = __float_as_uint(w[i]);
    atomicAdd(&g_hist[key >> 16], 1);
    // independent side work: zero adjacency bitset (2 MB = 131072 uint4)
    uint4 z = make_uint4(0u, 0u, 0u, 0u);
    ((uint4*)g_adj)[i] = z;
    ((uint4*)g_adj)[i + 65536] = z;
}

// ---------------- 1b) pick exact k-th largest, then self-zero hist ----------
__global__ void k_pick(const float* __restrict__ w, int k) {
    __shared__ int s_scan[1024];
    __shared__ unsigned s_cand[CAP_];
    __shared__ int s_n, s_bucket, s_krem;
    int tid = threadIdx.x;
    const int CHK = HB_ / 1024;   // 64 bins per thread, descending chunks

    int base = HB_ - 1 - tid * CHK;
    int psum = 0;
#pragma unroll 8
    for (int i = 0; i < CHK; i++) psum += g_hist[base - i];
    s_scan[tid] = psum;
    __syncthreads();
    for (int off = 1; off < 1024; off <<= 1) {
        int v = (tid >= off) ? s_scan[tid - off] : 0;
        __syncthreads();
        s_scan[tid] += v;
        __syncthreads();
    }
    int incl = s_scan[tid];
    int excl = incl - psum;
    if (excl < k && incl >= k) {
        int cum = excl;
        for (int i = 0; i < CHK; i++) {
            int b = base - i;
            int h = g_hist[b];
            cum += h;
            if (cum >= k) {
                s_bucket = b;
                s_krem = k - (cum - h);
                break;
            }
        }
    }
    if (tid == 0) s_n = 0;
    __syncthreads();
    // restore hist to zero for the next replay (all reads of g_hist are done)
#pragma unroll 8
    for (int i = 0; i < CHK; i++) g_hist[base - i] = 0;

    int bucket = s_bucket;
    for (int i = tid; i < E_; i += 1024) {
        unsigned key = __float_as_uint(w[i]);
        if ((int)(key >> 16) == bucket) {
            int p = atomicAdd(&s_n, 1);
            if (p < CAP_) s_cand[p] = key;
        }
    }
    __syncthreads();
    int n = s_n < CAP_ ? s_n : CAP_;
    int krem = s_krem;
    for (int i = tid; i < n; i += 1024) {
        unsigned v = s_cand[i];
        int gt = 0, eq = 0;
        for (int j = 0; j < n; j++) {
            unsigned u = s_cand[j];
            gt += (u > v);
            eq += (u == v);
        }
        if (gt < krem && krem <= gt + eq)
            g_thresh = __uint_as_float(v);
    }
}

// ---------------- 2) encoder: embed = relu(x @ W_enc + b_enc) --------------
// 256 threads (8 warps), 32 rows x 64 cols per block, grid 128.
// K staged by 50 (10 stages) with register-prefetch double buffering.
#define KB_ 50
#define NSTG_ (FIN_/KB_)   // 10 stages
__global__ __launch_bounds__(256) void k_encoder(
        const float* __restrict__ x,
        const float* __restrict__ Wenc,
        const float* __restrict__ benc) {
    __shared__ float xs[2][KB_][34];   // [buf][kk][row], padded
    __shared__ float ws[2][KB_][64];
    int tid  = threadIdx.x;
    int colg = tid & 15;               // 4 cols each
    int rowg = tid >> 4;               // 0..15 -> 2 rows each
    int r0 = blockIdx.x * 32;
    int row0 = rowg * 2;

    unsigned long long acc[4];
#pragma unroll
    for (int c = 0; c < 4; c++) acc[c] = 0ull;

    // per stage: x = 32*50 = 1600 floats (7 rounds), w = 800 float4 (4 rounds)
    float  xr[7];
    float4 wr[4];

    {   // prologue: load stage 0
#pragma unroll
        for (int j = 0; j < 7; j++) {
            int i = tid + j*256;
            xr[j] = (i < 1600) ? x[(r0 + i/KB_)*FIN_ + i%KB_] : 0.f;
        }
#pragma unroll
        for (int j = 0; j < 4; j++) {
            int i = tid + j*256;
            if (i < 800) wr[j] = *(const float4*)&Wenc[(i >> 4)*64 + (i & 15)*4];
        }
#pragma unroll
        for (int j = 0; j < 7; j++) {
            int i = tid + j*256;
            if (i < 1600) xs[0][i%KB_][i/KB_] = xr[j];
        }
#pragma unroll
        for (int j = 0; j < 4; j++) {
            int i = tid + j*256;
            if (i < 800) *(float4*)&ws[0][i >> 4][(i & 15)*4] = wr[j];
        }
    }
    __syncthreads();

    for (int s = 0; s < NSTG_; s++) {
        int buf = s & 1;
        if (s + 1 < NSTG_) {
            int k0 = (s + 1) * KB_;
#pragma unroll
            for (int j = 0; j < 7; j++) {
                int i = tid + j*256;
                xr[j] = (i < 1600) ? x[(r0 + i/KB_)*FIN_ + k0 + i%KB_] : 0.f;
            }
#pragma unroll
            for (int j = 0; j < 4; j++) {
                int i = tid + j*256;
                if (i < 800) wr[j] = *(const float4*)&Wenc[(k0 + (i >> 4))*64 + (i & 15)*4];
            }
        }
#pragma unroll 10
        for (int kk = 0; kk < KB_; kk++) {
            float a0 = xs[buf][kk][row0];
            float a1 = xs[buf][kk][row0 + 1];
            unsigned long long a = pack2(a0, a1);
            float4 b = *(const float4*)&ws[buf][kk][colg*4];
            fma2(acc[0], a, pack2(b.x, b.x));
            fma2(acc[1], a, pack2(b.y, b.y));
            fma2(acc[2], a, pack2(b.z, b.z));
            fma2(acc[3], a, pack2(b.w, b.w));
        }
        if (s + 1 < NSTG_) {
            int nb = buf ^ 1;
#pragma unroll
            for (int j = 0; j < 7; j++) {
                int i = tid + j*256;
                if (i < 1600) xs[nb][i%KB_][i/KB_] = xr[j];
            }
#pragma unroll
            for (int j = 0; j < 4; j++) {
                int i = tid + j*256;
                if (i < 800) *(float4*)&ws[nb][i >> 4][(i & 15)*4] = wr[j];
            }
        }
        __syncthreads();
    }

    int col0 = colg * 4;
    int r = r0 + row0;
#pragma unroll
    for (int c = 0; c < 4; c++) {
        float bv = benc[col0 + c];
        float v0, v1;
        unpack2(acc[c], v0, v1);
        v0 += bv; v1 += bv;
        g_embed[(r+0)*64 + col0 + c] = v0 > 0.f ? v0 : 0.f;
        g_embed[(r+1)*64 + col0 + c] = v1 > 0.f ? v1 : 0.f;
    }
}

// ---------------- 3) adjacency bitset ---------------------------------------
__global__ void k_adj(const int* __restrict__ ei, const float* __restrict__ ew) {
    int i = blockIdx.x * blockDim.x + threadIdx.x;
    float th = g_thresh;
    if (i < E_) {
        if (ew[i] >= th) {
            int s = ei[i], d = ei[E_ + i];
            atomicOr(&g_adj[s*NW_ + (d >> 5)], 1u << (d & 31));
        }
    } else if (i < E_ + N_) {
        int n = i - E_;
        atomicOr(&g_adj[n*NW_ + (n >> 5)], 1u << (n & 31));   // diag
    }
}

// ---------------- 5) anchors (in-block) + class assign + log_softmax --------
__global__ void k_cls(const int* __restrict__ aidx,
                      const float* __restrict__ Wpred,
                      const float* __restrict__ bpred,
                      float* __restrict__ out) {
    __shared__ float sa[C_][64];
    __shared__ float sa2[C_];
    __shared__ float swp[64*C_];
    __shared__ float sbp[C_];
    int tid = threadIdx.x;           // 128
    if (tid < 64) {
        int h = tid;
        for (int c = 0; c < C_; c++) {
            float s = 0.f;
#pragma unroll 5
            for (int a = 0; a < A_; a++)
                s += g_embed[aidx[c*A_ + a]*64 + h];
            sa[c][h] = s * (1.f / A_);
        }
    } else {
        for (int i = tid - 64; i < 64*C_; i += 64) swp[i] = Wpred[i];
        if (tid - 64 < C_) sbp[tid - 64] = bpred[tid - 64];
    }
    __syncthreads();
    if (tid < C_) {
        float s = 0.f;
        for (int h = 0; h < 64; h++) { float v = sa[tid][h]; s += v*v; }
        sa2[tid] = s;
    }
    __syncthreads();

    int n = blockIdx.x * 128 + tid;
    float e[64];
    const float4* ep = (const float4*)(g_embed + n*64);
#pragma unroll
    for (int i = 0; i < 16; i++) {
        float4 v = ep[i];
        e[4*i] = v.x; e[4*i+1] = v.y; e[4*i+2] = v.z; e[4*i+3] = v.w;
    }
    float en2 = 0.f;
#pragma unroll
    for (int h = 0; h < 64; h++) en2 += e[h]*e[h];
    int best = 0; float bd = 3.4e38f;
    for (int c = 0; c < C_; c++) {
        float dot = 0.f;
#pragma unroll
        for (int h = 0; h < 64; h++) dot += e[h] * sa[c][h];
        float d2 = en2 - 2.f*dot + sa2[c];
        if (d2 < bd) { bd = d2; best = c; }
    }
    g_cls[n] = best;
    float xo[C_];
    for (int c = 0; c < C_; c++) {
        float s = sbp[c];
#pragma unroll
        for (int h = 0; h < 64; h++) s += e[h] * swp[h*C_ + c];
        xo[c] = s;
    }
    float m = xo[0];
    for (int c = 1; c < C_; c++) m = fmaxf(m, xo[c]);
    float se = 0.f;
    for (int c = 0; c < C_; c++) se += expf(xo[c] - m);
    float ls = logf(se);
    for (int c = 0; c < C_; c++) out[2*B_ + n*C_ + c] = xo[c] - m - ls;
}

// ---------------- 6) 2-hop reachability -------------------------------------
__global__ void k_hop2() {
    int i = blockIdx.x;
    int t = threadIdx.x;           // word-column 0..127
    __shared__ unsigned row[NW_];
    row[t] = g_adj[i*NW_ + t];
    __syncthreads();
    unsigned acc = row[t];
    for (int w = 0; w < NW_; w++) {
        unsigned bits = row[w];
        while (bits) {
            int b = __ffs(bits) - 1;
            bits &= bits - 1;
            int j = w*32 + b;
            acc |= g_adj[j*NW_ + t];
        }
    }
    g_hop2[i*NW_ + t] = acc;
}

// ---------------- 7) sparse class-mean per query -----------------------------
__global__ void k_cmean(const int* __restrict__ ego,
                        const int* __restrict__ pos,
                        const int* __restrict__ neg) {
    int q = blockIdx.x;
    int v;
    if (q < B_)          v = ego[q];
    else if (q < 2*B_)   v = pos[q - B_];
    else                 v = neg[q - 2*B_];

    __shared__ float sums[CH_];
    __shared__ int   cnt[C_];
    __shared__ int   list[4096];
    __shared__ int   nlist;
    int tid = threadIdx.x;
    for (int i = tid; i < CH_; i += blockDim.x) sums[i] = 0.f;
    if (tid < C_) cnt[tid] = 0;
    if (tid == 0) nlist = 0;
    __syncthreads();

    for (int w = tid; w < NW_; w += blockDim.x) {
        unsigned bits = g_hop2[v*NW_ + w];
        while (bits) {
            int b = __ffs(bits) - 1;
            bits &= bits - 1;
            int p = atomicAdd(&nlist, 1);
            list[p] = w*32 + b;
        }
    }
    __syncthreads();
    int M = nlist;
    int lane = tid & 31, warp = tid >> 5;
    for (int li = warp; li < M; li += (int)(blockDim.x >> 5)) {
        int n = list[li];
        int c = g_cls[n];
        atomicAdd(&sums[c*64 + lane],      g_embed[n*64 + lane]);
        atomicAdd(&sums[c*64 + lane + 32], g_embed[n*64 + lane + 32]);
        if (lane == 0) atomicAdd(&cnt[c], 1);
    }
    __syncthreads();
    for (int i = tid; i < CH_; i += blockDim.x) {
        int c = i >> 6;
        float cc = (float)(cnt[c] > 0 ? cnt[c] : 1);
        g_red[q*CH_ + i] = sums[i] / cc;
    }
}

// ---------------- 8) decoder MLP on (e-p)^2 and (e-n)^2 ----------------------
__global__ void k_dec(const float* __restrict__ W1, const float* __restrict__ b1,
                      const float* __restrict__ W2, const float* __restrict__ b2,
                      float* __restrict__ out) {
    int b = blockIdx.x;
    __shared__ float op[CH_], on[CH_];
    __shared__ float part[4][32];
    int tid = threadIdx.x;
    const float* er = g_red + (size_t)b*CH_;
    const float* pr = g_red + (size_t)(B_ + b)*CH_;
    const float* nr = g_red + (size_t)(2*B_ + b)*CH_;
    for (int i = tid; i < CH_; i += 128) {
        float e = er[i];
        float dp = e - pr[i]; op[i] = dp*dp;
        float dn = e - nr[i]; on[i] = dn*dn;
    }
    __syncthreads();
    int lane = tid & 31, warp = tid >> 5;
    const float* o = (warp < 2) ? op : on;
    int i0 = (warp & 1) * 224;
    float h = 0.f;
    for (int i = i0; i < i0 + 224; i++)
        h += o[i] * W1[i*32 + lane];
    part[warp][lane] = h;
    __syncthreads();
    if (warp == 0) {
        float hv = part[0][lane] + part[1][lane] + b1[lane];
        hv = hv > 0.f ? hv : 0.f;
        float v = hv * W2[lane];
        for (int o2 = 16; o2 > 0; o2 >>= 1) v += __shfl_down_sync(0xffffffffu, v, o2);
        if (lane == 0) out[b] = v + b2[0];
    } else if (warp == 1) {
        float hv = part[2][lane] + part[3][lane] + b1[lane];
        hv = hv > 0.f ? hv : 0.f;
        float v = hv * W2[lane];
        for (int o2 = 16; o2 > 0; o2 >>= 1) v += __shfl_down_sync(0xffffffffu, v, o2);
        if (lane == 0) out[B_ + b] = v + b2[0];
    }
}

// ---------------- stream fork resources (host-side, created at load) --------
struct HxStreams {
    cudaStream_t s2 = nullptr;
    cudaEvent_t  fork = nullptr, join = nullptr;
    bool ok = false;
    HxStreams() {
        if (cudaStreamCreateWithFlags(&s2, cudaStreamNonBlocking) != cudaSuccess) return;
        if (cudaEventCreateWithFlags(&fork, cudaEventDisableTiming) != cudaSuccess) return;
        if (cudaEventCreateWithFlags(&join, cudaEventDisableTiming) != cudaSuccess) return;
        ok = true;
    }
};
static HxStreams hx;

// ---------------- launch ------------------------------------------------------
extern "C" void kernel_launch(void* const* d_in, const int* in_sizes, int n_in,
                              void* d_out, int out_size) {
    const float* x    = (const float*)d_in[0];
    const int*   ei   = (const int*)  d_in[1];
    const int*   ego  = (const int*)  d_in[2];
    const int*   pos  = (const int*)  d_in[3];
    const int*   neg  = (const int*)  d_in[4];
    const float* ew   = (const float*)d_in[5];
    const int*   aidx = (const int*)  d_in[6];
    int wb = (in_sizes[7] == FIN_*H_) ? 7 : 8;
    const float* Wenc  = (const float*)d_in[wb + 0];
    const float* benc  = (const float*)d_in[wb + 1];
    const float* Wpred = (const float*)d_in[wb + 2];
    const float* bpred = (const float*)d_in[wb + 3];
    const float* W1    = (const float*)d_in[wb + 4];
    const float* b1    = (const float*)d_in[wb + 5];
    const float* W2    = (const float*)d_in[wb + 6];
    const float* b2    = (const float*)d_in[wb + 7];
    float* out = (float*)d_out;

    if (hx.ok) {
        // fork: encoder+cls chain runs parallel to hist->pick->adj->hop2 chain
        cudaEventRecord(hx.fork, 0);
        cudaStreamWaitEvent(hx.s2, hx.fork, 0);

        k_hist <<<256, 256>>>(ew);
        k_pick <<<1, 1024>>>(ew, E_/2);
        k_adj  <<<(E_ + N_ + 255)/256, 256>>>(ei, ew);
        k_hop2 <<<N_, 128>>>();

        k_encoder<<<N_/32, 256, 0, hx.s2>>>(x, Wenc, benc);
        k_cls    <<<N_/128, 128, 0, hx.s2>>>(aidx, Wpred, bpred, out);
        cudaEventRecord(hx.join, hx.s2);
        cudaStreamWaitEvent(0, hx.join, 0);

        k_cmean<<<3*B_, 256>>>(ego, pos, neg);
        k_dec  <<<B_, 128>>>(W1, b1, W2, b2, out);
    } else {
        k_hist   <<<256, 256>>>(ew);
        k_pick   <<<1, 1024>>>(ew, E_/2);
        k_encoder<<<N_/32, 256>>>(x, Wenc, benc);
        k_adj    <<<(E_ + N_ + 255)/256, 256>>>(ei, ew);
        k_cls    <<<N_/128, 128>>>(aidx, Wpred, bpred, out);
        k_hop2   <<<N_, 128>>>();
        k_cmean  <<<3*B_, 256>>>(ego, pos, neg);
        k_dec    <<<B_, 128>>>(W1, b1, W2, b2, out);
    }
}

// round 5
// speedup vs baseline: 1.1390x; 1.1390x over previous
#include <cuda_runtime.h>
#include <cuda_bf16.h>

#define N_    4096
#define FIN_  500
#define H_    64
#define C_    7
#define E_    65536
#define B_    1024
#define A_    20
#define NW_   128          // bitset words per row (4096 bits)
#define CH_   (C_*H_)      // 448
#define HB_   (1 << 16)    // 16-bit histogram bins
#define CAP_  2048         // candidate cap in k_pick

// ---------------- scratch (device globals; zero at module load) -------------
__device__ float    g_embed[N_*H_];        // 1 MB
__device__ unsigned g_adj  [N_*NW_];       // 2 MB
__device__ int      g_cls  [N_];
__device__ float    g_thresh;
__device__ int      g_hist [HB_];          // 256 KB
__device__ float    g_red[3*B_*CH_];       // 5.5 MB

// ---------------- packed f32x2 helpers --------------------------------------
__device__ __forceinline__ unsigned long long pack2(float lo, float hi) {
    unsigned long long v;
    asm("mov.b64 %0, {%1, %2};" : "=l"(v) : "f"(lo), "f"(hi));
    return v;
}
__device__ __forceinline__ void unpack2(unsigned long long v, float& lo, float& hi) {
    asm("mov.b64 {%0, %1}, %2;" : "=f"(lo), "=f"(hi) : "l"(v));
}
__device__ __forceinline__ void fma2(unsigned long long& d,
                                     unsigned long long a, unsigned long long b) {
    asm("fma.rn.f32x2 %0, %1, %2, %0;" : "+l"(d) : "l"(a), "l"(b));
}

// ---------------- 1a) histogram of edge weights + zero g_adj ----------------
// g_hist arrives zeroed (module load on run 1, k_pick self-zero afterwards).
__global__ void k_hist(const float* __restrict__ w) {
    int i = blockIdx.x * blockDim.x + threadIdx.x;       // 65536 threads
    unsigned key = __float_as_uint(w[i]);
    atomicAdd(&g_hist[key >> 16], 1);
    // independent side work: zero adjacency bitset (2 MB = 131072 uint4)
    uint4 z = make_uint4(0u, 0u, 0u, 0u);
    ((uint4*)g_adj)[i] = z;
    ((uint4*)g_adj)[i + 65536] = z;
}

// ---------------- 1b) pick exact k-th largest, then self-zero hist ----------
__global__ void k_pick(const float* __restrict__ w, int k) {
    __shared__ int s_scan[1024];
    __shared__ unsigned s_cand[CAP_];
    __shared__ int s_n, s_bucket, s_krem;
    int tid = threadIdx.x;
    const int CHK = HB_ / 1024;   // 64 bins per thread, descending chunks

    int base = HB_ - 1 - tid * CHK;
    int psum = 0;
#pragma unroll 8
    for (int i = 0; i < CHK; i++) psum += g_hist[base - i];
    s_scan[tid] = psum;
    __syncthreads();
    for (int off = 1; off < 1024; off <<= 1) {
        int v = (tid >= off) ? s_scan[tid - off] : 0;
        __syncthreads();
        s_scan[tid] += v;
        __syncthreads();
    }
    int incl = s_scan[tid];
    int excl = incl - psum;
    if (excl < k && incl >= k) {
        int cum = excl;
        for (int i = 0; i < CHK; i++) {
            int b = base - i;
            int h = g_hist[b];
            cum += h;
            if (cum >= k) {
                s_bucket = b;
                s_krem = k - (cum - h);
                break;
            }
        }
    }
    if (tid == 0) s_n = 0;
    __syncthreads();
    // restore hist to zero for the next replay (all reads of g_hist are done)
#pragma unroll 8
    for (int i = 0; i < CHK; i++) g_hist[base - i] = 0;

    int bucket = s_bucket;
    for (int i = tid; i < E_; i += 1024) {
        unsigned key = __float_as_uint(w[i]);
        if ((int)(key >> 16) == bucket) {
            int p = atomicAdd(&s_n, 1);
            if (p < CAP_) s_cand[p] = key;
        }
    }
    __syncthreads();
    int n = s_n < CAP_ ? s_n : CAP_;
    int krem = s_krem;
    for (int i = tid; i < n; i += 1024) {
        unsigned v = s_cand[i];
        int gt = 0, eq = 0;
        for (int j = 0; j < n; j++) {
            unsigned u = s_cand[j];
            gt += (u > v);
            eq += (u == v);
        }
        if (gt < krem && krem <= gt + eq)
            g_thresh = __uint_as_float(v);
    }
}

// ---------------- 2) encoder: embed = relu(x @ W_enc + b_enc) --------------
#define KB_ 50
#define NSTG_ (FIN_/KB_)   // 10 stages
__global__ __launch_bounds__(256) void k_encoder(
        const float* __restrict__ x,
        const float* __restrict__ Wenc,
        const float* __restrict__ benc) {
    __shared__ float xs[2][KB_][34];
    __shared__ float ws[2][KB_][64];
    int tid  = threadIdx.x;
    int colg = tid & 15;
    int rowg = tid >> 4;
    int r0 = blockIdx.x * 32;
    int row0 = rowg * 2;

    unsigned long long acc[4];
#pragma unroll
    for (int c = 0; c < 4; c++) acc[c] = 0ull;

    float  xr[7];
    float4 wr[4];

    {   // prologue: load stage 0
#pragma unroll
        for (int j = 0; j < 7; j++) {
            int i = tid + j*256;
            xr[j] = (i < 1600) ? x[(r0 + i/KB_)*FIN_ + i%KB_] : 0.f;
        }
#pragma unroll
        for (int j = 0; j < 4; j++) {
            int i = tid + j*256;
            if (i < 800) wr[j] = *(const float4*)&Wenc[(i >> 4)*64 + (i & 15)*4];
        }
#pragma unroll
        for (int j = 0; j < 7; j++) {
            int i = tid + j*256;
            if (i < 1600) xs[0][i%KB_][i/KB_] = xr[j];
        }
#pragma unroll
        for (int j = 0; j < 4; j++) {
            int i = tid + j*256;
            if (i < 800) *(float4*)&ws[0][i >> 4][(i & 15)*4] = wr[j];
        }
    }
    __syncthreads();

    for (int s = 0; s < NSTG_; s++) {
        int buf = s & 1;
        if (s + 1 < NSTG_) {
            int k0 = (s + 1) * KB_;
#pragma unroll
            for (int j = 0; j < 7; j++) {
                int i = tid + j*256;
                xr[j] = (i < 1600) ? x[(r0 + i/KB_)*FIN_ + k0 + i%KB_] : 0.f;
            }
#pragma unroll
            for (int j = 0; j < 4; j++) {
                int i = tid + j*256;
                if (i < 800) wr[j] = *(const float4*)&Wenc[(k0 + (i >> 4))*64 + (i & 15)*4];
            }
        }
#pragma unroll 10
        for (int kk = 0; kk < KB_; kk++) {
            float a0 = xs[buf][kk][row0];
            float a1 = xs[buf][kk][row0 + 1];
            unsigned long long a = pack2(a0, a1);
            float4 b = *(const float4*)&ws[buf][kk][colg*4];
            fma2(acc[0], a, pack2(b.x, b.x));
            fma2(acc[1], a, pack2(b.y, b.y));
            fma2(acc[2], a, pack2(b.z, b.z));
            fma2(acc[3], a, pack2(b.w, b.w));
        }
        if (s + 1 < NSTG_) {
            int nb = buf ^ 1;
#pragma unroll
            for (int j = 0; j < 7; j++) {
                int i = tid + j*256;
                if (i < 1600) xs[nb][i%KB_][i/KB_] = xr[j];
            }
#pragma unroll
            for (int j = 0; j < 4; j++) {
                int i = tid + j*256;
                if (i < 800) *(float4*)&ws[nb][i >> 4][(i & 15)*4] = wr[j];
            }
        }
        __syncthreads();
    }

    int col0 = colg * 4;
    int r = r0 + row0;
#pragma unroll
    for (int c = 0; c < 4; c++) {
        float bv = benc[col0 + c];
        float v0, v1;
        unpack2(acc[c], v0, v1);
        v0 += bv; v1 += bv;
        g_embed[(r+0)*64 + col0 + c] = v0 > 0.f ? v0 : 0.f;
        g_embed[(r+1)*64 + col0 + c] = v1 > 0.f ? v1 : 0.f;
    }
}

// ---------------- 3) adjacency bitset ---------------------------------------
__global__ void k_adj(const int* __restrict__ ei, const float* __restrict__ ew) {
    int i = blockIdx.x * blockDim.x + threadIdx.x;
    float th = g_thresh;
    if (i < E_) {
        if (ew[i] >= th) {
            int s = ei[i], d = ei[E_ + i];
            atomicOr(&g_adj[s*NW_ + (d >> 5)], 1u << (d & 31));
        }
    } else if (i < E_ + N_) {
        int n = i - E_;
        atomicOr(&g_adj[n*NW_ + (n >> 5)], 1u << (n & 31));   // diag
    }
}

// ---------------- 5) anchors (in-block) + class assign + log_softmax --------
__global__ void k_cls(const int* __restrict__ aidx,
                      const float* __restrict__ Wpred,
                      const float* __restrict__ bpred,
                      float* __restrict__ out) {
    __shared__ float sa[C_][64];
    __shared__ float sa2[C_];
    __shared__ float swp[64*C_];
    __shared__ float sbp[C_];
    int tid = threadIdx.x;           // 128
    if (tid < 64) {
        int h = tid;
        for (int c = 0; c < C_; c++) {
            float s = 0.f;
#pragma unroll 5
            for (int a = 0; a < A_; a++)
                s += g_embed[aidx[c*A_ + a]*64 + h];
            sa[c][h] = s * (1.f / A_);
        }
    } else {
        for (int i = tid - 64; i < 64*C_; i += 64) swp[i] = Wpred[i];
        if (tid - 64 < C_) sbp[tid - 64] = bpred[tid - 64];
    }
    __syncthreads();
    if (tid < C_) {
        float s = 0.f;
        for (int h = 0; h < 64; h++) { float v = sa[tid][h]; s += v*v; }
        sa2[tid] = s;
    }
    __syncthreads();

    int n = blockIdx.x * 128 + tid;
    float e[64];
    const float4* ep = (const float4*)(g_embed + n*64);
#pragma unroll
    for (int i = 0; i < 16; i++) {
        float4 v = ep[i];
        e[4*i] = v.x; e[4*i+1] = v.y; e[4*i+2] = v.z; e[4*i+3] = v.w;
    }
    float en2 = 0.f;
#pragma unroll
    for (int h = 0; h < 64; h++) en2 += e[h]*e[h];
    int best = 0; float bd = 3.4e38f;
    for (int c = 0; c < C_; c++) {
        float dot = 0.f;
#pragma unroll
        for (int h = 0; h < 64; h++) dot += e[h] * sa[c][h];
        float d2 = en2 - 2.f*dot + sa2[c];
        if (d2 < bd) { bd = d2; best = c; }
    }
    g_cls[n] = best;
    float xo[C_];
    for (int c = 0; c < C_; c++) {
        float s = sbp[c];
#pragma unroll
        for (int h = 0; h < 64; h++) s += e[h] * swp[h*C_ + c];
        xo[c] = s;
    }
    float m = xo[0];
    for (int c = 1; c < C_; c++) m = fmaxf(m, xo[c]);
    float se = 0.f;
    for (int c = 0; c < C_; c++) se += expf(xo[c] - m);
    float ls = logf(se);
    for (int c = 0; c < C_; c++) out[2*B_ + n*C_ + c] = xo[c] - m - ls;
}

// ---------------- 7) fused 2-hop + sparse class-mean per query ---------------
// hop2[v] = adj[v] | OR_{j in adj[v]} adj[j]  (adj includes diag, so adj[v]
// itself appears via j=v). Computed on the fly in shared; only the 3072
// query rows are ever needed, so the standalone hop2 kernel is gone.
__global__ __launch_bounds__(256) void k_cmean(
        const int* __restrict__ ego,
        const int* __restrict__ pos,
        const int* __restrict__ neg) {
    int q = blockIdx.x;
    int v;
    if (q < B_)          v = ego[q];
    else if (q < 2*B_)   v = pos[q - B_];
    else                 v = neg[q - 2*B_];

    __shared__ unsigned hop[NW_];
    __shared__ int   list1[1024];     // 1-hop neighbors
    __shared__ int   n1;
    __shared__ float sums[CH_];
    __shared__ int   cnt[C_];
    __shared__ int   list[4096];      // 2-hop members
    __shared__ int   nlist;
    int tid = threadIdx.x;            // 256

    for (int i = tid; i < CH_; i += 256) sums[i] = 0.f;
    if (tid < C_) cnt[tid] = 0;
    if (tid == 0) { n1 = 0; nlist = 0; }
    if (tid < NW_) hop[tid] = g_adj[v*NW_ + tid];
    __syncthreads();

    // extract 1-hop neighbor list (parallel: one word per thread)
    if (tid < NW_) {
        unsigned bits = hop[tid];
        while (bits) {
            int b = __ffs(bits) - 1;
            bits &= bits - 1;
            int p = atomicAdd(&n1, 1);
            list1[p] = tid*32 + b;
        }
    }
    __syncthreads();
    int m1 = n1;

    // OR the adj rows of all 1-hop neighbors into hop (includes adj[v] via diag)
    if (tid < NW_) {
        unsigned acc = hop[tid];
        for (int j = 0; j < m1; j++)
            acc |= g_adj[list1[j]*NW_ + tid];
        hop[tid] = acc;
    }
    __syncthreads();

    // extract 2-hop member list
    if (tid < NW_) {
        unsigned bits = hop[tid];
        while (bits) {
            int b = __ffs(bits) - 1;
            bits &= bits - 1;
            int p = atomicAdd(&nlist, 1);
            list[p] = tid*32 + b;
        }
    }
    __syncthreads();

    int M = nlist;
    int lane = tid & 31, warp = tid >> 5;
    for (int li = warp; li < M; li += 8) {
        int n = list[li];
        int c = g_cls[n];
        atomicAdd(&sums[c*64 + lane],      g_embed[n*64 + lane]);
        atomicAdd(&sums[c*64 + lane + 32], g_embed[n*64 + lane + 32]);
        if (lane == 0) atomicAdd(&cnt[c], 1);
    }
    __syncthreads();
    for (int i = tid; i < CH_; i += 256) {
        int c = i >> 6;
        float cc = (float)(cnt[c] > 0 ? cnt[c] : 1);
        g_red[q*CH_ + i] = sums[i] / cc;
    }
}

// ---------------- 8) decoder MLP on (e-p)^2 and (e-n)^2 ----------------------
__global__ void k_dec(const float* __restrict__ W1, const float* __restrict__ b1,
                      const float* __restrict__ W2, const float* __restrict__ b2,
                      float* __restrict__ out) {
    int b = blockIdx.x;
    __shared__ float op[CH_], on[CH_];
    __shared__ float part[4][32];
    int tid = threadIdx.x;
    const float* er = g_red + (size_t)b*CH_;
    const float* pr = g_red + (size_t)(B_ + b)*CH_;
    const float* nr = g_red + (size_t)(2*B_ + b)*CH_;
    for (int i = tid; i < CH_; i += 128) {
        float e = er[i];
        float dp = e - pr[i]; op[i] = dp*dp;
        float dn = e - nr[i]; on[i] = dn*dn;
    }
    __syncthreads();
    int lane = tid & 31, warp = tid >> 5;
    const float* o = (warp < 2) ? op : on;
    int i0 = (warp & 1) * 224;
    float h = 0.f;
    for (int i = i0; i < i0 + 224; i++)
        h += o[i] * W1[i*32 + lane];
    part[warp][lane] = h;
    __syncthreads();
    if (warp == 0) {
        float hv = part[0][lane] + part[1][lane] + b1[lane];
        hv = hv > 0.f ? hv : 0.f;
        float v = hv * W2[lane];
        for (int o2 = 16; o2 > 0; o2 >>= 1) v += __shfl_down_sync(0xffffffffu, v, o2);
        if (lane == 0) out[b] = v + b2[0];
    } else if (warp == 1) {
        float hv = part[2][lane] + part[3][lane] + b1[lane];
        hv = hv > 0.f ? hv : 0.f;
        float v = hv * W2[lane];
        for (int o2 = 16; o2 > 0; o2 >>= 1) v += __shfl_down_sync(0xffffffffu, v, o2);
        if (lane == 0) out[B_ + b] = v + b2[0];
    }
}

// ---------------- stream fork resources (host-side, created at load) --------
struct HxStreams {
    cudaStream_t s2 = nullptr;
    cudaEvent_t  fork = nullptr, join = nullptr;
    bool ok = false;
    HxStreams() {
        if (cudaStreamCreateWithFlags(&s2, cudaStreamNonBlocking) != cudaSuccess) return;
        if (cudaEventCreateWithFlags(&fork, cudaEventDisableTiming) != cudaSuccess) return;
        if (cudaEventCreateWithFlags(&join, cudaEventDisableTiming) != cudaSuccess) return;
        ok = true;
    }
};
static HxStreams hx;

// ---------------- launch ------------------------------------------------------
extern "C" void kernel_launch(void* const* d_in, const int* in_sizes, int n_in,
                              void* d_out, int out_size) {
    const float* x    = (const float*)d_in[0];
    const int*   ei   = (const int*)  d_in[1];
    const int*   ego  = (const int*)  d_in[2];
    const int*   pos  = (const int*)  d_in[3];
    const int*   neg  = (const int*)  d_in[4];
    const float* ew   = (const float*)d_in[5];
    const int*   aidx = (const int*)  d_in[6];
    int wb = (in_sizes[7] == FIN_*H_) ? 7 : 8;
    const float* Wenc  = (const float*)d_in[wb + 0];
    const float* benc  = (const float*)d_in[wb + 1];
    const float* Wpred = (const float*)d_in[wb + 2];
    const float* bpred = (const float*)d_in[wb + 3];
    const float* W1    = (const float*)d_in[wb + 4];
    const float* b1    = (const float*)d_in[wb + 5];
    const float* W2    = (const float*)d_in[wb + 6];
    const float* b2    = (const float*)d_in[wb + 7];
    float* out = (float*)d_out;

    if (hx.ok) {
        // fork: encoder+cls chain runs parallel to hist->pick->adj chain
        cudaEventRecord(hx.fork, 0);
        cudaStreamWaitEvent(hx.s2, hx.fork, 0);

        k_hist <<<256, 256>>>(ew);
        k_pick <<<1, 1024>>>(ew, E_/2);
        k_adj  <<<(E_ + N_ + 255)/256, 256>>>(ei, ew);

        k_encoder<<<N_/32, 256, 0, hx.s2>>>(x, Wenc, benc);
        k_cls    <<<N_/128, 128, 0, hx.s2>>>(aidx, Wpred, bpred, out);
        cudaEventRecord(hx.join, hx.s2);
        cudaStreamWaitEvent(0, hx.join, 0);

        k_cmean<<<3*B_, 256>>>(ego, pos, neg);
        k_dec  <<<B_, 128>>>(W1, b1, W2, b2, out);
    } else {
        k_hist   <<<256, 256>>>(ew);
        k_pick   <<<1, 1024>>>(ew, E_/2);
        k_encoder<<<N_/32, 256>>>(x, Wenc, benc);
        k_adj    <<<(E_ + N_ + 255)/256, 256>>>(ei, ew);
        k_cls    <<<N_/128, 128>>>(aidx, Wpred, bpred, out);
        k_cmean  <<<3*B_, 256>>>(ego, pos, neg);
        k_dec    <<<B_, 128>>>(W1, b1, W2, b2, out);
    }
}